// round 13
// baseline (speedup 1.0000x reference)
#include <cuda_runtime.h>
#include <cuda_fp16.h>

#define NMAX 100000
#define EMAX 3200000
#define PEMAX (EMAX + 4 * NMAX)   // padded CSR capacity
#define NG 64
#define NC 10
#define SCANB 1024

// ---------------- device scratch ----------------
__device__ int gcn_degi[NMAX];          // in-degree; zeroed by k_mm1 after last read
__device__ int gcn_off[NMAX + 1];       // padded CSR row offsets (by dst), all %4==0
__device__ int gcn_cur[NMAX];           // fill cursors (overwritten every run)
__device__ int gcn_blocksum[128];
__device__ __align__(16) int gcn_csrc[PEMAX];
__device__ int gcn_batch[NMAX];
__device__ float gcn_dinv[NMAX];
__device__ __align__(16) uint4 gcn_bufA[NMAX + 1];  // [N] sentinel: never written, stays 0
__device__ __align__(16) uint4 gcn_bufB[NMAX + 1];
__device__ float gcn_pool[NG * NC];     // zeroed by k_out after read
__device__ float gcn_cnt[NG];
// staged per-pass weights/biases for the persistent layer kernel
__device__ float gcn_Wall[6][48];
__device__ float gcn_ball[6][8];
// software grid barrier: count self-resets; sense grows monotonically (replay-safe)
__device__ unsigned gb_count;
__device__ volatile unsigned gb_sense;

__device__ __forceinline__ uint4 pack6(const float* o) {
    uint4 r;
    __half2 h01 = __floats2half2_rn(o[0], o[1]);
    __half2 h23 = __floats2half2_rn(o[2], o[3]);
    __half2 h45 = __floats2half2_rn(o[4], o[5]);
    r.x = *(unsigned*)&h01;
    r.y = *(unsigned*)&h23;
    r.z = *(unsigned*)&h45;
    r.w = 0u;
    return r;
}

__device__ __forceinline__ void unpack_add(uint4 v, float* a) {
    float2 f0 = __half22float2(*(__half2*)&v.x);
    float2 f1 = __half22float2(*(__half2*)&v.y);
    float2 f2 = __half22float2(*(__half2*)&v.z);
    a[0] += f0.x; a[1] += f0.y; a[2] += f1.x; a[3] += f1.y; a[4] += f2.x; a[5] += f2.y;
}

__device__ __forceinline__ int detect_is64(const void* edge, int N) {
    __shared__ int s_is64;
    if (threadIdx.x < 32) {
        const long long* p = (const long long*)edge;
        int bad = 0;
        for (int t = threadIdx.x; t < 128; t += 32) {
            long long v = p[t];
            if (v < 0 || v >= (long long)N) bad = 1;
        }
        bad = __any_sync(0xffffffffu, bad);
        if (threadIdx.x == 0) s_is64 = bad ? 0 : 1;
    }
    __syncthreads();
    return s_is64;
}

// Pack-padded CSR walk, 4 threads/node, double-pack unroll.
__device__ __forceinline__ void row_accum(const uint4* __restrict__ vin,
                                          int pbase, int pend, int q, float* a) {
#pragma unroll
    for (int j = 0; j < 6; j++) a[j] = 0.0f;
    const int4* cp = (const int4*)gcn_csrc;
    int p = pbase + q;
#pragma unroll 1
    for (; p + 4 < pend; p += 8) {
        int4 s0 = __ldg(&cp[p]);
        int4 s1 = __ldg(&cp[p + 4]);
        uint4 v0 = __ldg(&vin[s0.x]);
        uint4 v1 = __ldg(&vin[s0.y]);
        uint4 v2 = __ldg(&vin[s0.z]);
        uint4 v3 = __ldg(&vin[s0.w]);
        uint4 v4 = __ldg(&vin[s1.x]);
        uint4 v5 = __ldg(&vin[s1.y]);
        uint4 v6 = __ldg(&vin[s1.z]);
        uint4 v7 = __ldg(&vin[s1.w]);
        unpack_add(v0, a); unpack_add(v1, a); unpack_add(v2, a); unpack_add(v3, a);
        unpack_add(v4, a); unpack_add(v5, a); unpack_add(v6, a); unpack_add(v7, a);
    }
    if (p < pend) {
        int4 s = __ldg(&cp[p]);
        uint4 v0 = __ldg(&vin[s.x]);
        uint4 v1 = __ldg(&vin[s.y]);
        uint4 v2 = __ldg(&vin[s.z]);
        uint4 v3 = __ldg(&vin[s.w]);
        unpack_add(v0, a); unpack_add(v1, a); unpack_add(v2, a); unpack_add(v3, a);
    }
}

// ---------------- degree histogram + batch counts (4 edges/thread) ----------
__global__ __launch_bounds__(256) void k_hist(const void* edge, const void* batchp,
                                              int N, int E) {
    int is64 = detect_is64(edge, N);
    int i = blockIdx.x * 256 + threadIdx.x;
    int i4 = i * 4;
    if (i4 + 3 < E) {
        int d0, d1, d2, d3;
        if (is64) {
            const longlong2* dp = (const longlong2*)((const long long*)edge + E);
            longlong2 p0 = __ldg(&dp[i * 2]);
            longlong2 p1 = __ldg(&dp[i * 2 + 1]);
            d0 = (int)p0.x; d1 = (int)p0.y; d2 = (int)p1.x; d3 = (int)p1.y;
        } else {
            int4 p = __ldg(&((const int4*)((const int*)edge + E))[i]);
            d0 = p.x; d1 = p.y; d2 = p.z; d3 = p.w;
        }
        atomicAdd(&gcn_degi[d0], 1);
        atomicAdd(&gcn_degi[d1], 1);
        atomicAdd(&gcn_degi[d2], 1);
        atomicAdd(&gcn_degi[d3], 1);
    } else {
        for (int e = i4; e < E; e++) {
            int d = is64 ? (int)((const long long*)edge)[(size_t)E + e]
                         : ((const int*)edge)[(size_t)E + e];
            atomicAdd(&gcn_degi[d], 1);
        }
    }
    if (i < N) {
        int b = is64 ? (int)((const long long*)batchp)[i] : ((const int*)batchp)[i];
        gcn_batch[i] = b;
        atomicAdd(&gcn_cnt[b], 1.0f);
    }
}

// -------- scan phase 1: per-block exclusive scan of PADDED degree ----------
__global__ __launch_bounds__(SCANB) void k_scan1(int N) {
    __shared__ int s[SCANB];
    int t = threadIdx.x;
    int i = blockIdx.x * SCANB + t;
    int v = (i < N) ? ((gcn_degi[i] + 3) & ~3) : 0;
    s[t] = v;
    __syncthreads();
    for (int d = 1; d < SCANB; d <<= 1) {
        int x = (t >= d) ? s[t - d] : 0;
        __syncthreads();
        s[t] += x;
        __syncthreads();
    }
    if (i < N) gcn_off[i] = s[t] - v;
    if (t == SCANB - 1) gcn_blocksum[blockIdx.x] = s[t];
}

// -------- scan phase 2+3 fused (+ row padding) ----------
__global__ __launch_bounds__(256) void k_scan3(int N, int nblk) {
    __shared__ int bs[128];
    int t = threadIdx.x;
    if (t < 128) {
        int v = (t < nblk) ? gcn_blocksum[t] : 0;
        bs[t] = v;
    }
    __syncthreads();
    if (t < 128) {
        for (int d = 1; d < 128; d <<= 1) {
            int x = (t >= d) ? bs[t - d] : 0;
            __syncthreads();
            bs[t] += x;
            __syncthreads();
        }
    } else {
        for (int d = 1; d < 128; d <<= 1) { __syncthreads(); __syncthreads(); }
    }
    __syncthreads();
    int i = blockIdx.x * 256 + t;
    if (i < N) {
        int blk = i >> 10;
        int base = (blk == 0) ? 0 : bs[blk - 1];
        int o = gcn_off[i] + base;
        gcn_off[i] = o;
        gcn_cur[i] = o;
        int deg = gcn_degi[i];
        int pdeg = (deg + 3) & ~3;
        for (int e = o + deg; e < o + pdeg; e++) gcn_csrc[e] = N;
        if (i == N - 1) gcn_off[N] = o + pdeg;
    }
}

// ---------------- CSR fill (counting sort, 4 edges/thread) ----------------
__global__ __launch_bounds__(256) void k_fill(const void* edge, int N, int E) {
    int is64 = detect_is64(edge, N);
    int i = blockIdx.x * 256 + threadIdx.x;
    int i4 = i * 4;
    if (i4 + 3 < E) {
        int s0, s1, s2, s3, d0, d1, d2, d3;
        if (is64) {
            const longlong2* sp = (const longlong2*)edge;
            const longlong2* dp = (const longlong2*)((const long long*)edge + E);
            longlong2 a0 = __ldg(&sp[i * 2]), a1 = __ldg(&sp[i * 2 + 1]);
            longlong2 b0 = __ldg(&dp[i * 2]), b1 = __ldg(&dp[i * 2 + 1]);
            s0 = (int)a0.x; s1 = (int)a0.y; s2 = (int)a1.x; s3 = (int)a1.y;
            d0 = (int)b0.x; d1 = (int)b0.y; d2 = (int)b1.x; d3 = (int)b1.y;
        } else {
            int4 a = __ldg(&((const int4*)edge)[i]);
            int4 b = __ldg(&((const int4*)((const int*)edge + E))[i]);
            s0 = a.x; s1 = a.y; s2 = a.z; s3 = a.w;
            d0 = b.x; d1 = b.y; d2 = b.z; d3 = b.w;
        }
        gcn_csrc[atomicAdd(&gcn_cur[d0], 1)] = s0;
        gcn_csrc[atomicAdd(&gcn_cur[d1], 1)] = s1;
        gcn_csrc[atomicAdd(&gcn_cur[d2], 1)] = s2;
        gcn_csrc[atomicAdd(&gcn_cur[d3], 1)] = s3;
    } else {
        for (int e = i4; e < E; e++) {
            int s, d;
            if (is64) {
                s = (int)((const long long*)edge)[e];
                d = (int)((const long long*)edge)[(size_t)E + e];
            } else {
                s = ((const int*)edge)[e];
                d = ((const int*)edge)[(size_t)E + e];
            }
            gcn_csrc[atomicAdd(&gcn_cur[d], 1)] = s;
        }
    }
}

// ---------------- stage per-pass weights/biases ----------------
__global__ void k_stage(const float* W2, const float* W3, const float* W4,
                        const float* W5, const float* W6,
                        const float* b1, const float* b2, const float* b3,
                        const float* b4, const float* b5, const float* b6) {
    int t = threadIdx.x;
    const float* Ws[5] = {W2, W3, W4, W5, W6};
    const float* bs[6] = {b1, b2, b3, b4, b5, b6};
    if (t < 288) {                   // 6 passes x 48
        int p = t / 48, r = t % 48;
        int k = r >> 3, j = r & 7;
        float v = 0.0f;
        if (p < 5 && j < 6) v = Ws[p][k * 6 + j];
        gcn_Wall[p][r] = v;
    } else if (t < 336) {            // 6 passes x 8
        int p = (t - 288) / 8, j = (t - 288) % 8;
        gcn_ball[p][j] = (j < 6) ? bs[p][j] : 0.0f;
    }
}

// ---------------- layer-1 transform (4 lanes/row, 128-thr blocks) -----------
__global__ __launch_bounds__(128) void k_mm1(const float* __restrict__ x,
                                             const float* __restrict__ W, int N) {
    __shared__ float sW[128 * 8];
    for (int t = threadIdx.x; t < 1024; t += 128) {
        int k = t >> 3, j = t & 7;
        sW[t] = (j < 6) ? W[k * 6 + j] : 0.0f;
    }
    __syncthreads();
    int g = blockIdx.x * 128 + threadIdx.x;
    int i = g >> 2;
    int q = g & 3;
    if (i >= N) return;
    const float4* xr = (const float4*)(x + (size_t)i * 128) + q * 8;
    float a[6];
#pragma unroll
    for (int j = 0; j < 6; j++) a[j] = 0.0f;
#pragma unroll
    for (int k4 = 0; k4 < 8; k4++) {
        float4 xv = xr[k4];
        const float* wp = &sW[(q * 8 + k4) * 32];
#pragma unroll
        for (int j = 0; j < 6; j++) {
            a[j] += xv.x * wp[j] + xv.y * wp[8 + j] + xv.z * wp[16 + j] + xv.w * wp[24 + j];
        }
    }
#pragma unroll
    for (int j = 0; j < 6; j++) {
        a[j] += __shfl_xor_sync(0xffffffffu, a[j], 1);
        a[j] += __shfl_xor_sync(0xffffffffu, a[j], 2);
    }
    if (q == 0) {
        float dinv = rsqrtf((float)(gcn_degi[i] + 1));   // +1: self loop
        gcn_degi[i] = 0;                                 // self-clean for next replay
        gcn_dinv[i] = dinv;
        float o[6] = { a[0] * dinv, a[1] * dinv, a[2] * dinv,
                       a[3] * dinv, a[4] * dinv, a[5] * dinv };
        gcn_bufA[i] = pack6(o);
    }
}

// ---------------- software grid barrier (sense-monotonic, replay-safe) ------
__device__ __forceinline__ void grid_barrier(unsigned expected, int nblocks) {
    __syncthreads();
    if (threadIdx.x == 0) {
        __threadfence();   // release: prior STGs reach L2 before arrival
        unsigned a = atomicAdd(&gb_count, 1u);
        if (a == (unsigned)(nblocks - 1)) {
            gb_count = 0;                 // reset BEFORE releasing sense
            __threadfence();
            gb_sense = expected;          // volatile store: release
        } else {
            while (gb_sense < expected) { }   // volatile spin (L2)
        }
        __threadfence();   // acquire: invalidates this SM's L1D (CCTL.IVALL)
    }
    __syncthreads();
}

// ---- persistent kernel: 6 fused aggregation+epilogue passes, 5 barriers ----
__global__ __launch_bounds__(128, 8)
void k_layers(uint4* __restrict__ A, uint4* __restrict__ Bv, int N, int nblocks) {
    unsigned sense0 = gb_sense;   // safe: no release can precede everyone's entry
    __shared__ float sW[48];
    __shared__ float sb[6];
    int tid = threadIdx.x;
    int total = nblocks * 128;
    int work = 4 * N;
#pragma unroll 1
    for (int pass = 0; pass < 6; pass++) {
        bool applyW = (pass < 5);
        const uint4* vin  = (pass & 1) ? Bv : A;
        uint4*       vout = (pass & 1) ? A  : Bv;
        if (tid < 48) sW[tid] = gcn_Wall[pass][tid];
        if (tid < 6)  sb[tid] = gcn_ball[pass][tid];
        __syncthreads();
#pragma unroll 1
        for (int g0 = blockIdx.x * 128; g0 < work; g0 += total) {
            int g = g0 + tid;
            int i = g >> 2;
            int q = g & 3;
            bool valid = (i < N);
            int pbase = 0, pend = 0;
            if (valid) { pbase = gcn_off[i] >> 2; pend = gcn_off[i + 1] >> 2; }
            float a[6];
            row_accum(vin, pbase, pend, q, a);
#pragma unroll
            for (int j = 0; j < 6; j++) {
                a[j] += __shfl_xor_sync(0xffffffffu, a[j], 1);
                a[j] += __shfl_xor_sync(0xffffffffu, a[j], 2);
            }
            if (valid && q == 0) {
                unpack_add(__ldg(&vin[i]), a);   // self loop
                float dinv = gcn_dinv[i];
                float h[6];
#pragma unroll
                for (int j = 0; j < 6; j++) h[j] = fmaxf(dinv * a[j] + sb[j], 0.0f);
                float o[6];
                if (applyW) {
#pragma unroll
                    for (int j = 0; j < 6; j++) {
                        float s = 0.0f;
#pragma unroll
                        for (int k = 0; k < 6; k++) s += h[k] * sW[k * 8 + j];
                        o[j] = s * dinv;
                    }
                } else {
#pragma unroll
                    for (int j = 0; j < 6; j++) o[j] = h[j] * dinv;
                }
                vout[i] = pack6(o);
            }
        }
        if (pass < 5) grid_barrier(sense0 + (unsigned)pass + 1u, nblocks);
        else __syncthreads();
    }
}

// ---------------- final: CSR agg (4t/node) + (agg @ Wf + bf) relu + pool ----
__global__ __launch_bounds__(128) void k_csr_final(const uint4* __restrict__ vin,
                                                   const float* __restrict__ Wf,
                                                   const float* __restrict__ bf, int N) {
    __shared__ float sW[60];
    __shared__ float sb[10];
    __shared__ float sp[NG * NC];
    for (int t = threadIdx.x; t < NG * NC; t += 128) sp[t] = 0.0f;
    if (threadIdx.x < 60) sW[threadIdx.x] = Wf[threadIdx.x];
    if (threadIdx.x < 10) sb[threadIdx.x] = bf[threadIdx.x];
    __syncthreads();
    int g = blockIdx.x * 128 + threadIdx.x;
    int i = g >> 2;
    int q = g & 3;
    bool valid = (i < N);
    int pbase = 0, pend = 0;
    if (valid) { pbase = gcn_off[i] >> 2; pend = gcn_off[i + 1] >> 2; }

    float a[6];
    row_accum(vin, pbase, pend, q, a);
#pragma unroll
    for (int j = 0; j < 6; j++) {
        a[j] += __shfl_xor_sync(0xffffffffu, a[j], 1);
        a[j] += __shfl_xor_sync(0xffffffffu, a[j], 2);
    }
    if (valid && q == 0) {
        unpack_add(__ldg(&vin[i]), a);
        float dinv = gcn_dinv[i];
#pragma unroll
        for (int j = 0; j < 6; j++) a[j] *= dinv;
        int bg = gcn_batch[i];
#pragma unroll
        for (int c = 0; c < 10; c++) {
            float s = sb[c];
#pragma unroll
            for (int j = 0; j < 6; j++) s += a[j] * sW[j * 10 + c];
            s = fmaxf(s, 0.0f);
            atomicAdd(&sp[bg * 10 + c], s);
        }
    }
    __syncthreads();
    int first = blockIdx.x * 32;
    if (first >= N) return;
    int last = min(first + 31, N - 1);
    int bmin = gcn_batch[first], bmax = gcn_batch[last];   // batch sorted
    int cnt = (bmax - bmin + 1) * 10;
    for (int t = threadIdx.x; t < cnt; t += 128) {
        float v = sp[bmin * 10 + t];
        if (v != 0.0f) atomicAdd(&gcn_pool[bmin * 10 + t], v);
    }
}

// ------- mean + log_softmax; self-cleans pool/cnt for the next replay -------
__global__ void k_out(float* __restrict__ out) {
    int g = threadIdx.x;
    if (g < NG) {
        float cnt = fmaxf(gcn_cnt[g], 1.0f);
        float p[10];
        float m = -1e30f;
#pragma unroll
        for (int c = 0; c < 10; c++) {
            p[c] = gcn_pool[g * 10 + c] / cnt;
            m = fmaxf(m, p[c]);
        }
        float s = 0.0f;
#pragma unroll
        for (int c = 0; c < 10; c++) s += expf(p[c] - m);
        float l = logf(s);
#pragma unroll
        for (int c = 0; c < 10; c++) out[g * 10 + c] = p[c] - m - l;
    }
    __syncthreads();
    if (threadIdx.x < NG * NC) gcn_pool[threadIdx.x] = 0.0f;
    if (threadIdx.x < NG) gcn_cnt[threadIdx.x] = 0.0f;
}

// ---------------- launch ----------------
extern "C" void kernel_launch(void* const* d_in, const int* in_sizes, int n_in,
                              void* d_out, int out_size) {
    const float* x     = (const float*)d_in[0];
    const void*  edge  = d_in[1];
    const void*  batch = d_in[2];
    const float* W1 = (const float*)d_in[3];
    const float* b1 = (const float*)d_in[4];
    const float* W2 = (const float*)d_in[5];
    const float* b2 = (const float*)d_in[6];
    const float* W3 = (const float*)d_in[7];
    const float* b3 = (const float*)d_in[8];
    const float* W4 = (const float*)d_in[9];
    const float* b4 = (const float*)d_in[10];
    const float* W5 = (const float*)d_in[11];
    const float* b5 = (const float*)d_in[12];
    const float* W6 = (const float*)d_in[13];
    const float* b6 = (const float*)d_in[14];
    const float* Wf = (const float*)d_in[15];
    const float* bf = (const float*)d_in[16];

    int N = in_sizes[0] / 128;
    int E = in_sizes[1] / 2;
    float* out = (float*)d_out;

    int nb_n  = (N + 255) / 256;
    int nb_e4 = ((E + 3) / 4 + 255) / 256;
    int nb_s  = (N + SCANB - 1) / SCANB;
    int nb_m4 = (4 * N + 127) / 128;   // 4 threads per node, 128-thr blocks

    void* pA; void* pB;
    cudaGetSymbolAddress(&pA, gcn_bufA);
    cudaGetSymbolAddress(&pB, gcn_bufB);
    uint4* A  = (uint4*)pA;
    uint4* Bv = (uint4*)pB;

    // persistent-kernel grid: guaranteed co-resident (occupancy-query sized)
    int dev = 0, sms = 148, occ = 1;
    cudaGetDevice(&dev);
    cudaDeviceGetAttribute(&sms, cudaDevAttrMultiProcessorCount, dev);
    cudaOccupancyMaxActiveBlocksPerMultiprocessor(&occ, k_layers, 128, 0);
    if (occ < 1) occ = 1;
    int nblocks = sms * occ;
    if (nblocks > nb_m4) nblocks = nb_m4;   // never more blocks than work groups

    k_hist<<<nb_e4, 256>>>(edge, batch, N, E);
    k_scan1<<<nb_s, SCANB>>>(N);
    k_scan3<<<nb_n, 256>>>(N, nb_s);
    k_fill<<<nb_e4, 256>>>(edge, N, E);
    k_stage<<<1, 384>>>(W2, W3, W4, W5, W6, b1, b2, b3, b4, b5, b6);

    k_mm1<<<nb_m4, 128>>>(x, W1, N);                 // -> A (g1); cleans degi
    k_layers<<<nblocks, 128>>>(A, Bv, N, nblocks);   // 6 fused passes -> A
    k_csr_final<<<nb_m4, 128>>>(A, Wf, bf, N);
    k_out<<<1, NG * NC>>>(out);                      // cleans pool/cnt
}

// round 14
// speedup vs baseline: 1.0619x; 1.0619x over previous
#include <cuda_runtime.h>
#include <cuda_fp16.h>

#define NMAX 100000
#define EMAX 3200000
#define PEMAX (EMAX + 4 * NMAX)   // padded CSR capacity
#define NG 64
#define NC 10
#define SCANB 1024

// ---------------- device scratch ----------------
__device__ int gcn_degi[NMAX];          // in-degree; zeroed by k_mm1 after last read
__device__ int gcn_off[NMAX + 1];       // padded CSR row offsets (by dst), all %4==0
__device__ int gcn_blocksum[128];
__device__ __align__(16) int gcn_rank[EMAX];   // per-edge within-dst rank (from k_hist)
__device__ __align__(16) int gcn_csrc[PEMAX];  // CSR column (src) indices, padded
__device__ int gcn_batch[NMAX];
__device__ float gcn_dinv[NMAX];
__device__ __align__(16) uint4 gcn_bufA[NMAX + 1];  // [N] sentinel: never written, stays 0
__device__ __align__(16) uint4 gcn_bufB[NMAX + 1];
__device__ float gcn_pool[NG * NC];     // zeroed by k_out after read
__device__ float gcn_cnt[NG];

__device__ __forceinline__ uint4 pack6(const float* o) {
    uint4 r;
    __half2 h01 = __floats2half2_rn(o[0], o[1]);
    __half2 h23 = __floats2half2_rn(o[2], o[3]);
    __half2 h45 = __floats2half2_rn(o[4], o[5]);
    r.x = *(unsigned*)&h01;
    r.y = *(unsigned*)&h23;
    r.z = *(unsigned*)&h45;
    r.w = 0u;
    return r;
}

__device__ __forceinline__ void unpack_add(uint4 v, float* a) {
    float2 f0 = __half22float2(*(__half2*)&v.x);
    float2 f1 = __half22float2(*(__half2*)&v.y);
    float2 f2 = __half22float2(*(__half2*)&v.z);
    a[0] += f0.x; a[1] += f0.y; a[2] += f1.x; a[3] += f1.y; a[4] += f2.x; a[5] += f2.y;
}

// Per-block int64-vs-int32 index detection (first 128 entries, L2-hot).
__device__ __forceinline__ int detect_is64(const void* edge, int N) {
    __shared__ int s_is64;
    if (threadIdx.x < 32) {
        const long long* p = (const long long*)edge;
        int bad = 0;
        for (int t = threadIdx.x; t < 128; t += 32) {
            long long v = p[t];
            if (v < 0 || v >= (long long)N) bad = 1;
        }
        bad = __any_sync(0xffffffffu, bad);
        if (threadIdx.x == 0) s_is64 = bad ? 0 : 1;
    }
    __syncthreads();
    return s_is64;
}

// Pack-padded CSR walk, 4 threads/node, double-pack unroll.
__device__ __forceinline__ void row_accum(const uint4* __restrict__ vin,
                                          int pbase, int pend, int q, float* a) {
#pragma unroll
    for (int j = 0; j < 6; j++) a[j] = 0.0f;
    const int4* cp = (const int4*)gcn_csrc;
    int p = pbase + q;
#pragma unroll 1
    for (; p + 4 < pend; p += 8) {
        int4 s0 = __ldg(&cp[p]);
        int4 s1 = __ldg(&cp[p + 4]);
        uint4 v0 = __ldg(&vin[s0.x]);
        uint4 v1 = __ldg(&vin[s0.y]);
        uint4 v2 = __ldg(&vin[s0.z]);
        uint4 v3 = __ldg(&vin[s0.w]);
        uint4 v4 = __ldg(&vin[s1.x]);
        uint4 v5 = __ldg(&vin[s1.y]);
        uint4 v6 = __ldg(&vin[s1.z]);
        uint4 v7 = __ldg(&vin[s1.w]);
        unpack_add(v0, a); unpack_add(v1, a); unpack_add(v2, a); unpack_add(v3, a);
        unpack_add(v4, a); unpack_add(v5, a); unpack_add(v6, a); unpack_add(v7, a);
    }
    if (p < pend) {
        int4 s = __ldg(&cp[p]);
        uint4 v0 = __ldg(&vin[s.x]);
        uint4 v1 = __ldg(&vin[s.y]);
        uint4 v2 = __ldg(&vin[s.z]);
        uint4 v3 = __ldg(&vin[s.w]);
        unpack_add(v0, a); unpack_add(v1, a); unpack_add(v2, a); unpack_add(v3, a);
    }
}

// ------ degree histogram + per-edge rank capture + batch counts -------------
// The atomicAdd return value IS the edge's within-destination rank; storing it
// coalesced lets k_fill run atomic-free.
__global__ __launch_bounds__(256) void k_hist(const void* edge, const void* batchp,
                                              int N, int E) {
    int is64 = detect_is64(edge, N);
    int i = blockIdx.x * 256 + threadIdx.x;
    int i4 = i * 4;
    if (i4 + 3 < E) {
        int d0, d1, d2, d3;
        if (is64) {
            const longlong2* dp = (const longlong2*)((const long long*)edge + E);
            longlong2 p0 = __ldg(&dp[i * 2]);
            longlong2 p1 = __ldg(&dp[i * 2 + 1]);
            d0 = (int)p0.x; d1 = (int)p0.y; d2 = (int)p1.x; d3 = (int)p1.y;
        } else {
            int4 p = __ldg(&((const int4*)((const int*)edge + E))[i]);
            d0 = p.x; d1 = p.y; d2 = p.z; d3 = p.w;
        }
        int4 r;
        r.x = atomicAdd(&gcn_degi[d0], 1);
        r.y = atomicAdd(&gcn_degi[d1], 1);
        r.z = atomicAdd(&gcn_degi[d2], 1);
        r.w = atomicAdd(&gcn_degi[d3], 1);
        ((int4*)gcn_rank)[i] = r;            // coalesced rank store
    } else {
        for (int e = i4; e < E; e++) {
            int d = is64 ? (int)((const long long*)edge)[(size_t)E + e]
                         : ((const int*)edge)[(size_t)E + e];
            gcn_rank[e] = atomicAdd(&gcn_degi[d], 1);
        }
    }
    if (i < N) {
        int b = is64 ? (int)((const long long*)batchp)[i] : ((const int*)batchp)[i];
        gcn_batch[i] = b;
        atomicAdd(&gcn_cnt[b], 1.0f);
    }
}

// -------- scan phase 1: per-block exclusive scan of PADDED degree ----------
__global__ __launch_bounds__(SCANB) void k_scan1(int N) {
    __shared__ int s[SCANB];
    int t = threadIdx.x;
    int i = blockIdx.x * SCANB + t;
    int v = (i < N) ? ((gcn_degi[i] + 3) & ~3) : 0;
    s[t] = v;
    __syncthreads();
    for (int d = 1; d < SCANB; d <<= 1) {
        int x = (t >= d) ? s[t - d] : 0;
        __syncthreads();
        s[t] += x;
        __syncthreads();
    }
    if (i < N) gcn_off[i] = s[t] - v;
    if (t == SCANB - 1) gcn_blocksum[blockIdx.x] = s[t];
}

// -------- scan phase 2+3 fused (+ row padding) ----------
__global__ __launch_bounds__(256) void k_scan3(int N, int nblk) {
    __shared__ int bs[128];
    int t = threadIdx.x;
    if (t < 128) {
        int v = (t < nblk) ? gcn_blocksum[t] : 0;
        bs[t] = v;
    }
    __syncthreads();
    if (t < 128) {
        for (int d = 1; d < 128; d <<= 1) {
            int x = (t >= d) ? bs[t - d] : 0;
            __syncthreads();
            bs[t] += x;
            __syncthreads();
        }
    } else {
        for (int d = 1; d < 128; d <<= 1) { __syncthreads(); __syncthreads(); }
    }
    __syncthreads();
    int i = blockIdx.x * 256 + t;
    if (i < N) {
        int blk = i >> 10;
        int base = (blk == 0) ? 0 : bs[blk - 1];
        int o = gcn_off[i] + base;
        gcn_off[i] = o;
        int deg = gcn_degi[i];
        int pdeg = (deg + 3) & ~3;
        for (int e = o + deg; e < o + pdeg; e++) gcn_csrc[e] = N;  // sentinel pad
        if (i == N - 1) gcn_off[N] = o + pdeg;
    }
}

// --------- CSR fill: ATOMIC-FREE scatter using precomputed ranks ------------
__global__ __launch_bounds__(256) void k_fill(const void* edge, int N, int E) {
    int is64 = detect_is64(edge, N);
    int i = blockIdx.x * 256 + threadIdx.x;
    int i4 = i * 4;
    if (i4 + 3 < E) {
        int s0, s1, s2, s3, d0, d1, d2, d3;
        if (is64) {
            const longlong2* sp = (const longlong2*)edge;
            const longlong2* dp = (const longlong2*)((const long long*)edge + E);
            longlong2 a0 = __ldg(&sp[i * 2]), a1 = __ldg(&sp[i * 2 + 1]);
            longlong2 b0 = __ldg(&dp[i * 2]), b1 = __ldg(&dp[i * 2 + 1]);
            s0 = (int)a0.x; s1 = (int)a0.y; s2 = (int)a1.x; s3 = (int)a1.y;
            d0 = (int)b0.x; d1 = (int)b0.y; d2 = (int)b1.x; d3 = (int)b1.y;
        } else {
            int4 a = __ldg(&((const int4*)edge)[i]);
            int4 b = __ldg(&((const int4*)((const int*)edge + E))[i]);
            s0 = a.x; s1 = a.y; s2 = a.z; s3 = a.w;
            d0 = b.x; d1 = b.y; d2 = b.z; d3 = b.w;
        }
        int4 r = ((const int4*)gcn_rank)[i];
        int o0 = __ldg(&gcn_off[d0]);
        int o1 = __ldg(&gcn_off[d1]);
        int o2 = __ldg(&gcn_off[d2]);
        int o3 = __ldg(&gcn_off[d3]);
        gcn_csrc[o0 + r.x] = s0;
        gcn_csrc[o1 + r.y] = s1;
        gcn_csrc[o2 + r.z] = s2;
        gcn_csrc[o3 + r.w] = s3;
    } else {
        for (int e = i4; e < E; e++) {
            int s, d;
            if (is64) {
                s = (int)((const long long*)edge)[e];
                d = (int)((const long long*)edge)[(size_t)E + e];
            } else {
                s = ((const int*)edge)[e];
                d = ((const int*)edge)[(size_t)E + e];
            }
            gcn_csrc[__ldg(&gcn_off[d]) + gcn_rank[e]] = s;
        }
    }
}

// ---------------- layer-1 transform (4 lanes/row, 128-thr blocks) -----------
// Also self-cleans gcn_degi for the next graph replay (last reader).
__global__ __launch_bounds__(128) void k_mm1(const float* __restrict__ x,
                                             const float* __restrict__ W, int N) {
    __shared__ float sW[128 * 8];
    for (int t = threadIdx.x; t < 1024; t += 128) {
        int k = t >> 3, j = t & 7;
        sW[t] = (j < 6) ? W[k * 6 + j] : 0.0f;
    }
    __syncthreads();
    int g = blockIdx.x * 128 + threadIdx.x;
    int i = g >> 2;
    int q = g & 3;
    if (i >= N) return;
    const float4* xr = (const float4*)(x + (size_t)i * 128) + q * 8;
    float a[6];
#pragma unroll
    for (int j = 0; j < 6; j++) a[j] = 0.0f;
#pragma unroll
    for (int k4 = 0; k4 < 8; k4++) {
        float4 xv = xr[k4];
        const float* wp = &sW[(q * 8 + k4) * 32];
#pragma unroll
        for (int j = 0; j < 6; j++) {
            a[j] += xv.x * wp[j] + xv.y * wp[8 + j] + xv.z * wp[16 + j] + xv.w * wp[24 + j];
        }
    }
#pragma unroll
    for (int j = 0; j < 6; j++) {
        a[j] += __shfl_xor_sync(0xffffffffu, a[j], 1);
        a[j] += __shfl_xor_sync(0xffffffffu, a[j], 2);
    }
    if (q == 0) {
        float dinv = rsqrtf((float)(gcn_degi[i] + 1));   // +1: self loop
        gcn_degi[i] = 0;                                 // self-clean for next replay
        gcn_dinv[i] = dinv;
        float o[6] = { a[0] * dinv, a[1] * dinv, a[2] * dinv,
                       a[3] * dinv, a[4] * dinv, a[5] * dinv };
        gcn_bufA[i] = pack6(o);
    }
}

// --- fused CSR aggregation (4 threads/node, 128-thr blocks) + epilogue ------
template <bool APPLY_W>
__global__ __launch_bounds__(128) void k_csr(const uint4* __restrict__ vin,
                                             uint4* __restrict__ vout,
                                             const float* __restrict__ b,
                                             const float* __restrict__ W, int N) {
    __shared__ float sW[48];
    __shared__ float sb[6];
    if (threadIdx.x < 48) {
        int k = threadIdx.x >> 3, j = threadIdx.x & 7;
        sW[threadIdx.x] = (APPLY_W && j < 6) ? W[k * 6 + j] : 0.0f;
    }
    if (threadIdx.x < 6) sb[threadIdx.x] = b[threadIdx.x];
    __syncthreads();
    int g = blockIdx.x * 128 + threadIdx.x;
    int i = g >> 2;
    int q = g & 3;
    bool valid = (i < N);
    int pbase = 0, pend = 0;
    if (valid) { pbase = gcn_off[i] >> 2; pend = gcn_off[i + 1] >> 2; }

    float a[6];
    row_accum(vin, pbase, pend, q, a);

#pragma unroll
    for (int j = 0; j < 6; j++) {
        a[j] += __shfl_xor_sync(0xffffffffu, a[j], 1);
        a[j] += __shfl_xor_sync(0xffffffffu, a[j], 2);
    }
    if (!valid || q != 0) return;

    unpack_add(__ldg(&vin[i]), a);       // self loop
    float dinv = gcn_dinv[i];
    float h[6];
#pragma unroll
    for (int j = 0; j < 6; j++) h[j] = fmaxf(dinv * a[j] + sb[j], 0.0f);
    float o[6];
    if (APPLY_W) {
#pragma unroll
        for (int j = 0; j < 6; j++) {
            float s = 0.0f;
#pragma unroll
            for (int k = 0; k < 6; k++) s += h[k] * sW[k * 8 + j];
            o[j] = s * dinv;
        }
    } else {
#pragma unroll
        for (int j = 0; j < 6; j++) o[j] = h[j] * dinv;
    }
    vout[i] = pack6(o);
}

// ---------------- final: CSR agg (4t/node) + (agg @ Wf + bf) relu + pool ----
__global__ __launch_bounds__(128) void k_csr_final(const uint4* __restrict__ vin,
                                                   const float* __restrict__ Wf,
                                                   const float* __restrict__ bf, int N) {
    __shared__ float sW[60];
    __shared__ float sb[10];
    __shared__ float sp[NG * NC];
    for (int t = threadIdx.x; t < NG * NC; t += 128) sp[t] = 0.0f;
    if (threadIdx.x < 60) sW[threadIdx.x] = Wf[threadIdx.x];
    if (threadIdx.x < 10) sb[threadIdx.x] = bf[threadIdx.x];
    __syncthreads();
    int g = blockIdx.x * 128 + threadIdx.x;
    int i = g >> 2;
    int q = g & 3;
    bool valid = (i < N);
    int pbase = 0, pend = 0;
    if (valid) { pbase = gcn_off[i] >> 2; pend = gcn_off[i + 1] >> 2; }

    float a[6];
    row_accum(vin, pbase, pend, q, a);
#pragma unroll
    for (int j = 0; j < 6; j++) {
        a[j] += __shfl_xor_sync(0xffffffffu, a[j], 1);
        a[j] += __shfl_xor_sync(0xffffffffu, a[j], 2);
    }
    if (valid && q == 0) {
        unpack_add(__ldg(&vin[i]), a);
        float dinv = gcn_dinv[i];
#pragma unroll
        for (int j = 0; j < 6; j++) a[j] *= dinv;
        int bg = gcn_batch[i];
#pragma unroll
        for (int c = 0; c < 10; c++) {
            float s = sb[c];
#pragma unroll
            for (int j = 0; j < 6; j++) s += a[j] * sW[j * 10 + c];
            s = fmaxf(s, 0.0f);
            atomicAdd(&sp[bg * 10 + c], s);
        }
    }
    __syncthreads();
    int first = blockIdx.x * 32;           // 32 nodes per block (4 threads each)
    if (first >= N) return;
    int last = min(first + 31, N - 1);
    int bmin = gcn_batch[first], bmax = gcn_batch[last];   // batch sorted
    int cnt = (bmax - bmin + 1) * 10;
    for (int t = threadIdx.x; t < cnt; t += 128) {
        float v = sp[bmin * 10 + t];
        if (v != 0.0f) atomicAdd(&gcn_pool[bmin * 10 + t], v);
    }
}

// ------- mean + log_softmax; self-cleans pool/cnt for the next replay -------
__global__ void k_out(float* __restrict__ out) {
    int g = threadIdx.x;
    if (g < NG) {
        float cnt = fmaxf(gcn_cnt[g], 1.0f);
        float p[10];
        float m = -1e30f;
#pragma unroll
        for (int c = 0; c < 10; c++) {
            p[c] = gcn_pool[g * 10 + c] / cnt;
            m = fmaxf(m, p[c]);
        }
        float s = 0.0f;
#pragma unroll
        for (int c = 0; c < 10; c++) s += expf(p[c] - m);
        float l = logf(s);
#pragma unroll
        for (int c = 0; c < 10; c++) out[g * 10 + c] = p[c] - m - l;
    }
    __syncthreads();
    if (threadIdx.x < NG * NC) gcn_pool[threadIdx.x] = 0.0f;   // self-clean
    if (threadIdx.x < NG) gcn_cnt[threadIdx.x] = 0.0f;
}

// ---------------- launch ----------------
extern "C" void kernel_launch(void* const* d_in, const int* in_sizes, int n_in,
                              void* d_out, int out_size) {
    const float* x     = (const float*)d_in[0];
    const void*  edge  = d_in[1];
    const void*  batch = d_in[2];
    const float* W1 = (const float*)d_in[3];
    const float* b1 = (const float*)d_in[4];
    const float* W2 = (const float*)d_in[5];
    const float* b2 = (const float*)d_in[6];
    const float* W3 = (const float*)d_in[7];
    const float* b3 = (const float*)d_in[8];
    const float* W4 = (const float*)d_in[9];
    const float* b4 = (const float*)d_in[10];
    const float* W5 = (const float*)d_in[11];
    const float* b5 = (const float*)d_in[12];
    const float* W6 = (const float*)d_in[13];
    const float* b6 = (const float*)d_in[14];
    const float* Wf = (const float*)d_in[15];
    const float* bf = (const float*)d_in[16];

    int N = in_sizes[0] / 128;
    int E = in_sizes[1] / 2;
    float* out = (float*)d_out;

    int nb_n  = (N + 255) / 256;
    int nb_e4 = ((E + 3) / 4 + 255) / 256;
    int nb_s  = (N + SCANB - 1) / SCANB;
    int nb_m4 = (4 * N + 127) / 128;   // 4 threads per node, 128-thr blocks

    void* pA; void* pB;
    cudaGetSymbolAddress(&pA, gcn_bufA);
    cudaGetSymbolAddress(&pB, gcn_bufB);
    uint4* A  = (uint4*)pA;
    uint4* Bv = (uint4*)pB;

    k_hist<<<nb_e4, 256>>>(edge, batch, N, E);
    k_scan1<<<nb_s, SCANB>>>(N);
    k_scan3<<<nb_n, 256>>>(N, nb_s);    // fused scan2 + scan3 + pad
    k_fill<<<nb_e4, 256>>>(edge, N, E); // atomic-free scatter

    k_mm1<<<nb_m4, 128>>>(x, W1, N);                        // -> A (g1); cleans degi
    k_csr<true><<<nb_m4, 128>>>(A, Bv, b1, W2, N);          // -> B (g2)
    k_csr<true><<<nb_m4, 128>>>(Bv, A, b2, W3, N);          // -> A (g3)
    k_csr<true><<<nb_m4, 128>>>(A, Bv, b3, W4, N);          // -> B (g4)
    k_csr<true><<<nb_m4, 128>>>(Bv, A, b4, W5, N);          // -> A (g5)
    k_csr<true><<<nb_m4, 128>>>(A, Bv, b5, W6, N);          // -> B (g6)
    k_csr<false><<<nb_m4, 128>>>(Bv, A, b6, nullptr, N);    // -> A (h6*dinv)
    k_csr_final<<<nb_m4, 128>>>(A, Wf, bf, N);
    k_out<<<1, NG * NC>>>(out);                             // cleans pool/cnt
}